// round 2
// baseline (speedup 1.0000x reference)
#include <cuda_runtime.h>
#include <math.h>

#define TLEN 262144
#define KST  64
#define FDIM 16
#define LCH  512
#define WARM 256
#define NCH  (TLEN/LCH)
#define EPSV 1e-10
#define LOGEPS (-23.025850929940456840)

// ---- scratch (__device__ globals; no cudaMalloc allowed) ----
__device__ float  g_E   [(size_t)TLEN*KST];
__device__ float  g_dirF[(size_t)TLEN*KST];
__device__ float  g_dirB[(size_t)TLEN*KST];
__device__ float  g_cF[TLEN];
__device__ float  g_cB[TLEN];
__device__ double g_SF[TLEN], g_SB[TLEN];
__device__ double g_LF[TLEN], g_LB[TLEN];
__device__ double g_lqF[TLEN], g_lqB[TLEN];
__device__ double g_part[512];
__device__ float  g_scF[TLEN], g_scB[TLEN];

// ---------------------------------------------------------------------------
// Emission: E[t,k] = exp(-0.5*sum_f (x-mu)^2*exp(-lv) - 0.5*sum_f lv - F/2*log2pi)
// ---------------------------------------------------------------------------
__global__ void emis_kernel(const float* __restrict__ obs,
                            const float* __restrict__ means,
                            const float* __restrict__ logvars) {
    __shared__ float mu_s[FDIM][KST];
    __shared__ float iv_s[FDIM][KST];
    __shared__ float ck_s[KST];
    __shared__ float xo_s[4][FDIM];
    const float LOG2PI = 1.8378770664093453f;
    int tid = threadIdx.x;

    for (int idx = tid; idx < KST * FDIM; idx += 256) {
        int k = idx >> 4, f = idx & 15;
        mu_s[f][k] = means[idx];
        iv_s[f][k] = expf(-logvars[idx]);
    }
    if (tid < KST) {
        float s = 0.f;
        #pragma unroll
        for (int f = 0; f < FDIM; f++) s += logvars[tid * FDIM + f];
        ck_s[tid] = -0.5f * s - 0.5f * (float)FDIM * LOG2PI;
    }
    int t0 = blockIdx.x * 4;
    if (tid < 4 * FDIM) xo_s[tid >> 4][tid & 15] = obs[(size_t)t0 * FDIM + tid];
    __syncthreads();

    int k = tid & 63, tl = tid >> 6;
    float acc = 0.f;
    #pragma unroll
    for (int f = 0; f < FDIM; f++) {
        float d = xo_s[tl][f] - mu_s[f][k];
        acc = fmaf(d * d, iv_s[f][k], acc);
    }
    g_E[(size_t)(t0 + tl) * KST + k] = expf(-0.5f * acc + ck_s[k]);
}

// ---------------------------------------------------------------------------
// Chunked direction recursions. blockIdx < NCH: forward chunk; else backward.
// 128 threads: output index j = tid>>1, half h = tid&1.
// Stores unnormalized per-step vector u_t (sum = c_t) and c_t.
// ---------------------------------------------------------------------------
__global__ void __launch_bounds__(128) chunk_kernel(
    const float* __restrict__ pi_logits,
    const float* __restrict__ beta_logits) {
    __shared__ float Pa[KST * KST];
    __shared__ float rm[KST], ri[KST];
    __shared__ __align__(16) float dbuf[2][KST];
    __shared__ float wsb[2][4];
    const unsigned FULL = 0xffffffffu;
    int tid = threadIdx.x, lane = tid & 31, warp = tid >> 5;
    int j = tid >> 1, h = tid & 1;

    for (int idx = tid; idx < KST * KST; idx += 128) Pa[idx] = pi_logits[idx];
    __syncthreads();
    if (tid < KST) {
        float m = -1e30f;
        for (int i = 0; i < KST; i++) m = fmaxf(m, Pa[tid * KST + i]);
        float s = 0.f;
        for (int i = 0; i < KST; i++) s += expf(Pa[tid * KST + i] - m);
        rm[tid] = m; ri[tid] = 1.f / s;
    }
    __syncthreads();

    bool bwd = (blockIdx.x >= NCH);
    int cb = bwd ? (int)blockIdx.x - NCH : (int)blockIdx.x;
    int sout0 = cb * LCH;

    float Preg[32];
    if (!bwd) {
        #pragma unroll
        for (int ii = 0; ii < 32; ii++) {
            int i = h * 32 + ii;
            Preg[ii] = expf(Pa[i * KST + j] - rm[i]) * ri[i];
        }
    } else {
        #pragma unroll
        for (int ii = 0; ii < 32; ii++) {
            int jj = h * 32 + ii;
            Preg[ii] = expf(Pa[j * KST + jj] - rm[j]) * ri[j];
        }
    }

    // ---- init carried state ----
    int sfirst;
    float myu;
    if (!bwd) {
        if (cb == 0) {
            sfirst = 1;
            float pr = 1.f;
            for (int i = 0; i < j; i++) {
                float sg = 1.f / (1.f + expf(-beta_logits[i]));
                pr *= (1.f - sg);
            }
            float bw = pr / (1.f + expf(-beta_logits[j]));
            myu = bw * g_E[j];                       // u_0 = stickbreak * E[0]
            if (h == 0) { dbuf[0][j] = myu; g_dirF[j] = myu; }
        } else {
            sfirst = sout0 - WARM;
            myu = 1.f / 64.f;
            if (h == 0) dbuf[0][j] = myu;
        }
    } else {
        if (cb == 0) {
            sfirst = 1;
            myu = 1.f / 64.f;                         // v_hat at m=0 (b=ones normalized)
            if (h == 0) {
                dbuf[0][j] = (1.f / 64.f) * g_E[(size_t)(TLEN - 1) * KST + j]; // premult e_{T-1}
                g_dirB[(size_t)(TLEN - 1) * KST + j] = 1.f / 64.f;
            }
            if (tid == 0) g_cB[0] = 1.0f;
        } else {
            sfirst = sout0 - WARM;
            int tws = TLEN - 1 - (sfirst - 1);
            myu = 1.f / 64.f;
            if (h == 0) dbuf[0][j] = (1.f / 64.f) * g_E[(size_t)tws * KST + j];
        }
    }
    // butterfly of myu -> raw warp sums (double-counted across h; convention sp = 2*sum)
    float w = myu;
    w += __shfl_xor_sync(FULL, w, 16); w += __shfl_xor_sync(FULL, w, 8);
    w += __shfl_xor_sync(FULL, w, 4);  w += __shfl_xor_sync(FULL, w, 2);
    w += __shfl_xor_sync(FULL, w, 1);
    if (lane == 0) wsb[0][warp] = w;
    __syncthreads();

    int send = sout0 + LCH;
    int cmin = bwd ? (sout0 > 1 ? sout0 : 1) : sout0;
    int par = 0;

    for (int s = sfirst; s < send; s++) {
        float sp = (wsb[par][0] + wsb[par][1]) + (wsb[par][2] + wsb[par][3]);
        if (tid == 0 && (s - 1) >= cmin) { (bwd ? g_cB : g_cF)[s - 1] = 0.5f * sp; }
        float inv = 2.0f / sp;   // = 1/c_{prev}

        const float* dc = &dbuf[par][h * 32];
        float a0 = 0.f, a1 = 0.f, a2 = 0.f, a3 = 0.f;
        #pragma unroll
        for (int ii = 0; ii < 32; ii += 4) {
            float4 dv = *reinterpret_cast<const float4*>(dc + ii);
            a0 = fmaf(dv.x, Preg[ii], a0);
            a1 = fmaf(dv.y, Preg[ii + 1], a1);
            a2 = fmaf(dv.z, Preg[ii + 2], a2);
            a3 = fmaf(dv.w, Preg[ii + 3], a3);
        }
        float acc = (a0 + a1) + (a2 + a3);
        acc += __shfl_xor_sync(FULL, acc, 1);        // combine i/j halves

        float u;
        if (!bwd) u = acc * inv * g_E[(size_t)s * KST + j];
        else      u = acc * inv;

        float ww = u;
        ww += __shfl_xor_sync(FULL, ww, 16); ww += __shfl_xor_sync(FULL, ww, 8);
        ww += __shfl_xor_sync(FULL, ww, 4);  ww += __shfl_xor_sync(FULL, ww, 2);
        ww += __shfl_xor_sync(FULL, ww, 1);

        int np = par ^ 1;
        if (!bwd) {
            if (h == 0) {
                dbuf[np][j] = u;
                if (s >= sout0) g_dirF[(size_t)s * KST + j] = u;
            }
        } else {
            int t = TLEN - 1 - s;
            if (h == 0) {
                dbuf[np][j] = u * g_E[(size_t)t * KST + j];   // premult e_t for next step
                if (s >= sout0) g_dirB[(size_t)t * KST + j] = u;
            }
        }
        if (lane == 0) wsb[np][warp] = ww;
        par = np;
        __syncthreads();
    }
    if (tid == 0) {
        float sp = (wsb[par][0] + wsb[par][1]) + (wsb[par][2] + wsb[par][3]);
        (bwd ? g_cB : g_cF)[send - 1] = 0.5f * sp;
    }
}

// ---------------------------------------------------------------------------
// Exact scale: log q_t = S_t + LSE_{j<=t} G_j ;  S = prefix sum of log(eps/c),
// G_0 = log q_0, G_j = -S_j. Two 2-level f64 scans (512 x 512).
// ---------------------------------------------------------------------------
__device__ __forceinline__ double lae(double a, double b) {
    double m = fmax(a, b), n = fmin(a, b);
    if (m <= -1e290) return m;
    return m + log1p(exp(n - m));
}

__global__ void scan_add_p1(int fb) {
    __shared__ double sm[512];
    const float* carr = fb ? g_cB : g_cF;
    double* S = fb ? g_SB : g_SF;
    int tid = threadIdx.x, idx = blockIdx.x * 512 + tid;
    double v = (idx == 0) ? 0.0 : (LOGEPS - log((double)carr[idx]));
    sm[tid] = v; __syncthreads();
    for (int off = 1; off < 512; off <<= 1) {
        double t = (tid >= off) ? sm[tid - off] : 0.0;
        __syncthreads();
        sm[tid] += t; __syncthreads();
    }
    S[idx] = sm[tid];
    if (tid == 511) g_part[blockIdx.x] = sm[tid];
}
__global__ void scan_add_p2() {
    __shared__ double sm[512];
    int tid = threadIdx.x;
    sm[tid] = g_part[tid]; __syncthreads();
    for (int off = 1; off < 512; off <<= 1) {
        double t = (tid >= off) ? sm[tid - off] : 0.0;
        __syncthreads();
        sm[tid] += t; __syncthreads();
    }
    g_part[tid] = (tid == 0) ? 0.0 : sm[tid - 1];
}
__global__ void scan_add_p3(int fb) {
    double* S = fb ? g_SB : g_SF;
    int idx = blockIdx.x * 512 + threadIdx.x;
    S[idx] += g_part[blockIdx.x];
}
__global__ void scan_lse_p1(int fb) {
    __shared__ double sm[512];
    const double* S = fb ? g_SB : g_SF;
    double* L = fb ? g_LB : g_LF;
    int tid = threadIdx.x, idx = blockIdx.x * 512 + tid;
    double g;
    if (idx == 0) g = fb ? -log(64.0) : log1p(EPSV / (double)g_cF[0]);
    else          g = -S[idx];
    sm[tid] = g; __syncthreads();
    for (int off = 1; off < 512; off <<= 1) {
        double t = (tid >= off) ? sm[tid - off] : -1e300;
        __syncthreads();
        sm[tid] = lae(sm[tid], t); __syncthreads();
    }
    L[idx] = sm[tid];
    if (tid == 511) g_part[blockIdx.x] = sm[tid];
}
__global__ void scan_lse_p2() {
    __shared__ double sm[512];
    int tid = threadIdx.x;
    sm[tid] = g_part[tid]; __syncthreads();
    for (int off = 1; off < 512; off <<= 1) {
        double t = (tid >= off) ? sm[tid - off] : -1e300;
        __syncthreads();
        sm[tid] = lae(sm[tid], t); __syncthreads();
    }
    g_part[tid] = (tid == 0) ? -1e300 : sm[tid - 1];
}
__global__ void scan_lse_p3(int fb) {
    const double* S = fb ? g_SB : g_SF;
    const double* L = fb ? g_LB : g_LF;
    double* lq = fb ? g_lqB : g_lqF;
    int idx = blockIdx.x * 512 + threadIdx.x;
    lq[idx] = S[idx] + lae(L[idx], g_part[blockIdx.x]);
}

// ---------------------------------------------------------------------------
// Per-t scale = p_t / c_t ; also writes log_likelihood.
// ---------------------------------------------------------------------------
__global__ void prescale_kernel(float* __restrict__ out) {
    int t = blockIdx.x * 256 + threadIdx.x;
    g_scF[t] = (float)(exp(-g_lqF[t]) / (double)g_cF[t]);
    int m = TLEN - 1 - t;
    g_scB[t] = (float)(exp(-g_lqB[m]) / (double)g_cB[m]);
    if (t == TLEN - 1)
        out[(size_t)2 * TLEN * KST] = (float)log(exp(-g_lqF[TLEN - 1]) + EPSV);
}

__global__ void finalize_kernel(float* __restrict__ out) {
    size_t i = (size_t)blockIdx.x * 256 + threadIdx.x;
    int t = (int)(i >> 6);
    out[i] = g_scF[t] * g_dirF[i];
    out[(size_t)TLEN * KST + i] = g_scB[t] * g_dirB[i];
}

// ---------------------------------------------------------------------------
extern "C" void kernel_launch(void* const* d_in, const int* in_sizes, int n_in,
                              void* d_out, int out_size) {
    const float* obs      = (const float*)d_in[0];
    const float* blogits  = (const float*)d_in[1];
    const float* pilogits = (const float*)d_in[2];
    const float* means    = (const float*)d_in[3];
    const float* logvars  = (const float*)d_in[4];
    float* out = (float*)d_out;

    emis_kernel<<<TLEN / 4, 256>>>(obs, means, logvars);
    chunk_kernel<<<2 * NCH, 128>>>(pilogits, blogits);
    for (int fb = 0; fb < 2; fb++) {
        scan_add_p1<<<512, 512>>>(fb);
        scan_add_p2<<<1, 512>>>();
        scan_add_p3<<<512, 512>>>(fb);
        scan_lse_p1<<<512, 512>>>(fb);
        scan_lse_p2<<<1, 512>>>();
        scan_lse_p3<<<512, 512>>>(fb);
    }
    prescale_kernel<<<TLEN / 256, 256>>>(out);
    finalize_kernel<<<(size_t)TLEN * KST / 256, 256>>>(out);
}

// round 3
// speedup vs baseline: 1.1266x; 1.1266x over previous
#include <cuda_runtime.h>
#include <math.h>

#define TLEN 262144
#define KST  64
#define FDIM 16
#define LCH  512
#define WARM 256
#define STEPS (WARM + LCH)     // 768
#define TILE 16
#define NTILES (STEPS / TILE)  // 48
#define NCH  (TLEN / LCH)      // 512
#define EPSV 1e-10
#define LOGEPS (-23.025850929940456840)

// ---- scratch (__device__ globals; no cudaMalloc allowed) ----
__device__ float  g_E   [(size_t)TLEN * KST];
__device__ float  g_dirF[(size_t)TLEN * KST];
__device__ float  g_dirB[(size_t)TLEN * KST];
__device__ float  g_cF[TLEN];
__device__ float  g_cB[TLEN];
__device__ double g_SF[TLEN], g_SB[TLEN];
__device__ double g_LF[TLEN], g_LB[TLEN];
__device__ double g_lqF[TLEN], g_lqB[TLEN];
__device__ double g_part[512];
__device__ float  g_scF[TLEN], g_scB[TLEN];

__device__ __forceinline__ void cp16(void* dst, const void* src) {
    unsigned ds = (unsigned)__cvta_generic_to_shared(dst);
    asm volatile("cp.async.ca.shared.global [%0], [%1], 16;" :: "r"(ds), "l"(src));
}
#define CP_COMMIT() asm volatile("cp.async.commit_group;")
#define CP_WAIT(n)  asm volatile("cp.async.wait_group %0;" :: "n"(n))

// ---------------------------------------------------------------------------
// Emission: E[t,k] = exp(-0.5*sum_f (x-mu)^2*exp(-lv) - 0.5*sum_f lv - F/2*log2pi)
// ---------------------------------------------------------------------------
__global__ void emis_kernel(const float* __restrict__ obs,
                            const float* __restrict__ means,
                            const float* __restrict__ logvars) {
    __shared__ float mu_s[FDIM][KST];
    __shared__ float iv_s[FDIM][KST];
    __shared__ float ck_s[KST];
    __shared__ float xo_s[4][FDIM];
    const float LOG2PI = 1.8378770664093453f;
    int tid = threadIdx.x;

    for (int idx = tid; idx < KST * FDIM; idx += 256) {
        int k = idx >> 4, f = idx & 15;
        mu_s[f][k] = means[idx];
        iv_s[f][k] = expf(-logvars[idx]);
    }
    if (tid < KST) {
        float s = 0.f;
        #pragma unroll
        for (int f = 0; f < FDIM; f++) s += logvars[tid * FDIM + f];
        ck_s[tid] = -0.5f * s - 0.5f * (float)FDIM * LOG2PI;
    }
    int t0 = blockIdx.x * 4;
    if (tid < 4 * FDIM) xo_s[tid >> 4][tid & 15] = obs[(size_t)t0 * FDIM + tid];
    __syncthreads();

    int k = tid & 63, tl = tid >> 6;
    float acc = 0.f;
    #pragma unroll
    for (int f = 0; f < FDIM; f++) {
        float d = xo_s[tl][f] - mu_s[f][k];
        acc = fmaf(d * d, iv_s[f][k], acc);
    }
    g_E[(size_t)(t0 + tl) * KST + k] = expf(-0.5f * acc + ck_s[k]);
}

// ---------------------------------------------------------------------------
// Chunked direction recursions with cp.async E-tile prefetch.
// blockIdx < NCH: forward chunk; else backward. 128 threads: j = tid>>1, h=tid&1.
// ---------------------------------------------------------------------------
__global__ void __launch_bounds__(128, 7) chunk_kernel(
    const float* __restrict__ pi_logits,
    const float* __restrict__ beta_logits) {
    __shared__ float Pa[KST * KST];
    __shared__ float rm[KST], ri[KST];
    __shared__ __align__(16) float Ebuf[2][TILE][KST];
    __shared__ __align__(16) float dbuf[2][KST];
    __shared__ __align__(16) float wsp[2][16];

    const unsigned FULL = 0xffffffffu;
    int tid = threadIdx.x, lane = tid & 31, warp = tid >> 5;
    int j = tid >> 1, h = tid & 1;

    for (int idx = tid; idx < KST * KST; idx += 128) Pa[idx] = pi_logits[idx];
    __syncthreads();
    if (tid < KST) {
        float m = -1e30f;
        for (int i = 0; i < KST; i++) m = fmaxf(m, Pa[tid * KST + i]);
        float s = 0.f;
        for (int i = 0; i < KST; i++) s += expf(Pa[tid * KST + i] - m);
        rm[tid] = m; ri[tid] = 1.f / s;
    }
    __syncthreads();

    const bool bwd = (blockIdx.x >= NCH);
    const int cb = bwd ? (int)blockIdx.x - NCH : (int)blockIdx.x;
    const int sout0 = cb * LCH;
    const int sfirst0 = sout0 - WARM;               // step index at slot 0
    const int sfirst_act = (cb == 0) ? 1 : sfirst0; // first active step
    const int send = sout0 + LCH;
    const int cmin = bwd ? (sout0 > 1 ? sout0 : 1) : sout0;
    const int init_par = (sfirst_act - sfirst0) & 1;

    float Preg[32];
    if (!bwd) {
        #pragma unroll
        for (int ii = 0; ii < 32; ii++) {
            int i = h * 32 + ii;
            Preg[ii] = expf(Pa[i * KST + j] - rm[i]) * ri[i];
        }
    } else {
        #pragma unroll
        for (int ii = 0; ii < 32; ii++) {
            int jj = h * 32 + ii;
            Preg[ii] = expf(Pa[j * KST + jj] - rm[j]) * ri[j];
        }
    }

    // ---- init carried state ----
    float myu;
    if (!bwd) {
        if (cb == 0) {
            float pr = 1.f;
            for (int i = 0; i < j; i++) {
                float sg = 1.f / (1.f + expf(-beta_logits[i]));
                pr *= (1.f - sg);
            }
            float bw = pr / (1.f + expf(-beta_logits[j]));
            myu = bw * g_E[j];
            if (h == 0) { dbuf[init_par][j] = myu; g_dirF[j] = myu; }
        } else {
            myu = 1.f / 64.f;
            if (h == 0) dbuf[init_par][j] = myu;
        }
    } else {
        myu = 1.f / 64.f;
        if (cb == 0) {
            if (h == 0) {
                dbuf[init_par][j] = (1.f / 64.f) * g_E[(size_t)(TLEN - 1) * KST + j];
                g_dirB[(size_t)(TLEN - 1) * KST + j] = 1.f / 64.f;
            }
            if (tid == 0) g_cB[0] = 1.0f;
        } else {
            int tws = TLEN - sfirst0;   // = TLEN-1-(sfirst0-1)
            if (h == 0) dbuf[init_par][j] = (1.f / 64.f) * g_E[(size_t)tws * KST + j];
        }
    }
    {
        float red = myu;
        red += __shfl_xor_sync(FULL, red, 16);
        red += __shfl_xor_sync(FULL, red, 8);
        red += __shfl_xor_sync(FULL, red, 4);
        if (lane < 4) wsp[init_par][warp * 4 + lane] = red;
    }

    // ---- prefetch tile 0 ----
    {
        int idx = tid * 8;
        int q = idx >> 6, k0 = idx & 63;
        int s = sfirst0 + q;
        int row = bwd ? (TLEN - 1 - s) : s;
        row = row < 0 ? 0 : (row > TLEN - 1 ? TLEN - 1 : row);
        const float* src = g_E + (size_t)row * KST + k0;
        cp16(&Ebuf[0][q][k0], src);
        cp16(&Ebuf[0][q][k0 + 4], src + 4);
    }
    CP_COMMIT();
    __syncthreads();

    int par = 0;
    for (int tb = 0; tb < NTILES; tb++) {
        if (tb + 1 < NTILES) {
            int idx = tid * 8;
            int q = idx >> 6, k0 = idx & 63;
            int s = sfirst0 + (tb + 1) * TILE + q;
            int row = bwd ? (TLEN - 1 - s) : s;
            row = row < 0 ? 0 : (row > TLEN - 1 ? TLEN - 1 : row);
            const float* src = g_E + (size_t)row * KST + k0;
            int buf = (tb + 1) & 1;
            cp16(&Ebuf[buf][q][k0], src);
            cp16(&Ebuf[buf][q][k0 + 4], src + 4);
            CP_COMMIT();
            CP_WAIT(1);
        } else {
            CP_WAIT(0);
        }
        __syncthreads();

        const float* Etile = &Ebuf[tb & 1][0][0];
        #pragma unroll 4
        for (int st = 0; st < TILE; st++) {
            int s = sfirst0 + tb * TILE + st;
            bool active = (s >= sfirst_act);

            // block sum of previous step's u from 16 partials (overlaps the dot)
            const float* wp = wsp[par];
            float sp = ((wp[0] + wp[1]) + (wp[2] + wp[3]))
                     + ((wp[4] + wp[5]) + (wp[6] + wp[7]))
                     + ((wp[8] + wp[9]) + (wp[10] + wp[11]))
                     + ((wp[12] + wp[13]) + (wp[14] + wp[15]));
            float inv = __fdividef(2.f, sp);
            if (tid == 0 && active && (s - 1) >= cmin)
                (bwd ? g_cB : g_cF)[s - 1] = 0.5f * sp;

            const float* dc = &dbuf[par][h * 32];
            float a0 = 0.f, a1 = 0.f, a2 = 0.f, a3 = 0.f;
            #pragma unroll
            for (int ii = 0; ii < 32; ii += 4) {
                float4 dv = *reinterpret_cast<const float4*>(dc + ii);
                a0 = fmaf(dv.x, Preg[ii], a0);
                a1 = fmaf(dv.y, Preg[ii + 1], a1);
                a2 = fmaf(dv.z, Preg[ii + 2], a2);
                a3 = fmaf(dv.w, Preg[ii + 3], a3);
            }
            float acc = (a0 + a1) + (a2 + a3);
            acc += __shfl_xor_sync(FULL, acc, 1);
            float e = Etile[st * KST + j];
            int np = par ^ 1;

            if (active) {
                float u = bwd ? (acc * inv) : (acc * inv * e);
                if (h == 0) {
                    if (!bwd) {
                        dbuf[np][j] = u;
                        if (s >= sout0) g_dirF[(size_t)s * KST + j] = u;
                    } else {
                        dbuf[np][j] = u * e;
                        if (s >= sout0) g_dirB[(size_t)(TLEN - 1 - s) * KST + j] = u;
                    }
                }
                float red = u;
                red += __shfl_xor_sync(FULL, red, 16);
                red += __shfl_xor_sync(FULL, red, 8);
                red += __shfl_xor_sync(FULL, red, 4);
                if (lane < 4) wsp[np][warp * 4 + lane] = red;
            }
            par = np;
            __syncthreads();
        }
    }
    if (tid == 0) {
        const float* wp = wsp[par];
        float sp = 0.f;
        for (int i = 0; i < 16; i++) sp += wp[i];
        (bwd ? g_cB : g_cF)[send - 1] = 0.5f * sp;
    }
}

// ---------------------------------------------------------------------------
// Exact scale: log q_t = S_t + LSE_{j<=t} G_j ;  S = prefix sum of log(eps/c).
// ---------------------------------------------------------------------------
__device__ __forceinline__ double lae(double a, double b) {
    double m = fmax(a, b), n = fmin(a, b);
    if (m <= -1e290) return m;
    return m + log1p(exp(n - m));
}

__global__ void scan_add_p1(int fb) {
    __shared__ double sm[512];
    const float* carr = fb ? g_cB : g_cF;
    double* S = fb ? g_SB : g_SF;
    int tid = threadIdx.x, idx = blockIdx.x * 512 + tid;
    double v = (idx == 0) ? 0.0 : (LOGEPS - log((double)carr[idx]));
    sm[tid] = v; __syncthreads();
    for (int off = 1; off < 512; off <<= 1) {
        double t = (tid >= off) ? sm[tid - off] : 0.0;
        __syncthreads();
        sm[tid] += t; __syncthreads();
    }
    S[idx] = sm[tid];
    if (tid == 511) g_part[blockIdx.x] = sm[tid];
}
__global__ void scan_add_p2() {
    __shared__ double sm[512];
    int tid = threadIdx.x;
    sm[tid] = g_part[tid]; __syncthreads();
    for (int off = 1; off < 512; off <<= 1) {
        double t = (tid >= off) ? sm[tid - off] : 0.0;
        __syncthreads();
        sm[tid] += t; __syncthreads();
    }
    g_part[tid] = (tid == 0) ? 0.0 : sm[tid - 1];
}
__global__ void scan_add_p3(int fb) {
    double* S = fb ? g_SB : g_SF;
    int idx = blockIdx.x * 512 + threadIdx.x;
    S[idx] += g_part[blockIdx.x];
}
__global__ void scan_lse_p1(int fb) {
    __shared__ double sm[512];
    const double* S = fb ? g_SB : g_SF;
    double* L = fb ? g_LB : g_LF;
    int tid = threadIdx.x, idx = blockIdx.x * 512 + tid;
    double g;
    if (idx == 0) g = fb ? -log(64.0) : log1p(EPSV / (double)g_cF[0]);
    else          g = -S[idx];
    sm[tid] = g; __syncthreads();
    for (int off = 1; off < 512; off <<= 1) {
        double t = (tid >= off) ? sm[tid - off] : -1e300;
        __syncthreads();
        sm[tid] = lae(sm[tid], t); __syncthreads();
    }
    L[idx] = sm[tid];
    if (tid == 511) g_part[blockIdx.x] = sm[tid];
}
__global__ void scan_lse_p2() {
    __shared__ double sm[512];
    int tid = threadIdx.x;
    sm[tid] = g_part[tid]; __syncthreads();
    for (int off = 1; off < 512; off <<= 1) {
        double t = (tid >= off) ? sm[tid - off] : -1e300;
        __syncthreads();
        sm[tid] = lae(sm[tid], t); __syncthreads();
    }
    g_part[tid] = (tid == 0) ? -1e300 : sm[tid - 1];
}
__global__ void scan_lse_p3(int fb) {
    const double* S = fb ? g_SB : g_SF;
    const double* L = fb ? g_LB : g_LF;
    double* lq = fb ? g_lqB : g_lqF;
    int idx = blockIdx.x * 512 + threadIdx.x;
    lq[idx] = S[idx] + lae(L[idx], g_part[blockIdx.x]);
}

// ---------------------------------------------------------------------------
__global__ void prescale_kernel(float* __restrict__ out) {
    int t = blockIdx.x * 256 + threadIdx.x;
    g_scF[t] = (float)(exp(-g_lqF[t]) / (double)g_cF[t]);
    int m = TLEN - 1 - t;
    g_scB[t] = (float)(exp(-g_lqB[m]) / (double)g_cB[m]);
    if (t == TLEN - 1)
        out[(size_t)2 * TLEN * KST] = (float)log(exp(-g_lqF[TLEN - 1]) + EPSV);
}

__global__ void finalize_kernel(float* __restrict__ out) {
    size_t i4 = ((size_t)blockIdx.x * 256 + threadIdx.x) * 4;
    int t = (int)(i4 >> 6);
    float sF = g_scF[t], sB = g_scB[t];
    float4 a = *reinterpret_cast<const float4*>(&g_dirF[i4]);
    float4 b = *reinterpret_cast<const float4*>(&g_dirB[i4]);
    a.x *= sF; a.y *= sF; a.z *= sF; a.w *= sF;
    b.x *= sB; b.y *= sB; b.z *= sB; b.w *= sB;
    *reinterpret_cast<float4*>(&out[i4]) = a;
    *reinterpret_cast<float4*>(&out[(size_t)TLEN * KST + i4]) = b;
}

// ---------------------------------------------------------------------------
extern "C" void kernel_launch(void* const* d_in, const int* in_sizes, int n_in,
                              void* d_out, int out_size) {
    const float* obs      = (const float*)d_in[0];
    const float* blogits  = (const float*)d_in[1];
    const float* pilogits = (const float*)d_in[2];
    const float* means    = (const float*)d_in[3];
    const float* logvars  = (const float*)d_in[4];
    float* out = (float*)d_out;

    emis_kernel<<<TLEN / 4, 256>>>(obs, means, logvars);
    chunk_kernel<<<2 * NCH, 128>>>(pilogits, blogits);
    for (int fb = 0; fb < 2; fb++) {
        scan_add_p1<<<512, 512>>>(fb);
        scan_add_p2<<<1, 512>>>();
        scan_add_p3<<<512, 512>>>(fb);
        scan_lse_p1<<<512, 512>>>(fb);
        scan_lse_p2<<<1, 512>>>();
        scan_lse_p3<<<512, 512>>>(fb);
    }
    prescale_kernel<<<TLEN / 256, 256>>>(out);
    finalize_kernel<<<(size_t)TLEN * KST / 1024, 256>>>(out);
}

// round 4
// speedup vs baseline: 1.5927x; 1.4137x over previous
#include <cuda_runtime.h>
#include <math.h>

#define TLEN 262144
#define KST  64
#define FDIM 16
#define LCH  512
#define WARM 96
#define STEPS (WARM + LCH)     // 608
#define TILE 16
#define NTILES (STEPS / TILE)  // 38
#define NCH  (TLEN / LCH)      // 512
#define EPSV 1e-10
#define LOGEPS (-23.025850929940456840)

// ---- scratch (__device__ globals; no cudaMalloc allowed) ----
__device__ float  g_E   [(size_t)TLEN * KST];
__device__ float  g_dirF[(size_t)TLEN * KST];
__device__ float  g_dirB[(size_t)TLEN * KST];
__device__ float  g_cF[TLEN];
__device__ float  g_cB[TLEN];
__device__ double g_SF[TLEN], g_SB[TLEN];
__device__ double g_LF[TLEN], g_LB[TLEN];
__device__ double g_part[1024];
__device__ double g_part2[1024];
__device__ float  g_scF[TLEN], g_scB[TLEN];   // g_scB indexed in m-space (m = T-1-t)

typedef unsigned long long u64t;

__device__ __forceinline__ void fma2(u64t& acc, u64t a, u64t b) {
    asm("fma.rn.f32x2 %0, %1, %2, %3;" : "=l"(acc) : "l"(a), "l"(b), "l"(acc));
}
__device__ __forceinline__ void add2(u64t& d, u64t a, u64t b) {
    asm("add.rn.f32x2 %0, %1, %2;" : "=l"(d) : "l"(a), "l"(b));
}
__device__ __forceinline__ u64t pack2(float lo, float hi) {
    u64t r;
    asm("mov.b64 %0, {%1, %2};" : "=l"(r) : "f"(lo), "f"(hi));
    return r;
}
__device__ __forceinline__ float unpack_sum(u64t v) {
    float lo, hi;
    asm("mov.b64 {%0, %1}, %2;" : "=f"(lo), "=f"(hi) : "l"(v));
    return lo + hi;
}

__device__ __forceinline__ void cp16(void* dst, const void* src) {
    unsigned ds = (unsigned)__cvta_generic_to_shared(dst);
    asm volatile("cp.async.ca.shared.global [%0], [%1], 16;" :: "r"(ds), "l"(src));
}
#define CP_COMMIT() asm volatile("cp.async.commit_group;")
#define CP_WAIT(n)  asm volatile("cp.async.wait_group %0;" :: "n"(n))

// ---------------------------------------------------------------------------
// Emission
// ---------------------------------------------------------------------------
__global__ void emis_kernel(const float* __restrict__ obs,
                            const float* __restrict__ means,
                            const float* __restrict__ logvars) {
    __shared__ float mu_s[FDIM][KST];
    __shared__ float iv_s[FDIM][KST];
    __shared__ float ck_s[KST];
    __shared__ float xo_s[4][FDIM];
    const float LOG2PI = 1.8378770664093453f;
    int tid = threadIdx.x;

    for (int idx = tid; idx < KST * FDIM; idx += 256) {
        int k = idx >> 4, f = idx & 15;
        mu_s[f][k] = means[idx];
        iv_s[f][k] = expf(-logvars[idx]);
    }
    if (tid < KST) {
        float s = 0.f;
        #pragma unroll
        for (int f = 0; f < FDIM; f++) s += logvars[tid * FDIM + f];
        ck_s[tid] = -0.5f * s - 0.5f * (float)FDIM * LOG2PI;
    }
    int t0 = blockIdx.x * 4;
    if (tid < 4 * FDIM) xo_s[tid >> 4][tid & 15] = obs[(size_t)t0 * FDIM + tid];
    __syncthreads();

    int k = tid & 63, tl = tid >> 6;
    float acc = 0.f;
    #pragma unroll
    for (int f = 0; f < FDIM; f++) {
        float d = xo_s[tl][f] - mu_s[f][k];
        acc = fmaf(d * d, iv_s[f][k], acc);
    }
    g_E[(size_t)(t0 + tl) * KST + k] = expf(-0.5f * acc + ck_s[k]);
}

// ---------------------------------------------------------------------------
// Chunk kernel: block b runs fwd chunk b (threads 0..63) and bwd chunk b
// (threads 64..127). One output state per thread, f32x2 packed dot.
// ---------------------------------------------------------------------------
__global__ void __launch_bounds__(128, 4) chunk_kernel(
    const float* __restrict__ pi_logits,
    const float* __restrict__ beta_logits) {
    __shared__ float Pa[KST * KST];
    __shared__ float rm[KST], ri[KST];
    __shared__ __align__(16) float Ebuf[2][2][TILE][KST];
    __shared__ __align__(16) float dbuf[2][2][KST];   // [ch][par][k]
    __shared__ float wsp[2][4];                        // [par][warp]

    const unsigned FULL = 0xffffffffu;
    int tid = threadIdx.x, lane = tid & 31, warpid = tid >> 5;
    int ch = tid >> 6;          // 0 = fwd, 1 = bwd
    int jj = tid & 63;          // owned state

    const int cb = blockIdx.x;
    const int sout0 = cb * LCH;
    const int sfirst0 = sout0 - WARM;
    const int sfirst_act = (cb == 0) ? 1 : sfirst0;
    const int send = sout0 + LCH;
    const int cmin = (cb == 0) ? ((void)0, 0) : sout0;   // fwd cmin
    const int cminB = (sout0 > 1) ? sout0 : 1;           // bwd cmin (m-space)
    const int init_par = (sfirst_act - sfirst0) & 1;

    // Early prefetch of E tile 0 (independent of Pa setup)
    {
        #pragma unroll
        for (int i = 0; i < 4; i++) {
            int f = tid + i * 128;                 // float4 index, 512 total
            int c2 = f >> 8, q = (f >> 4) & 15, k0 = (f & 15) << 2;
            int s = sfirst0 + q;
            int row = c2 ? (TLEN - 1 - s) : s;
            row = row < 0 ? 0 : row;
            cp16(&Ebuf[0][c2][q][k0], g_E + (size_t)row * KST + k0);
        }
        CP_COMMIT();
    }

    for (int idx = tid; idx < KST * KST; idx += 128) Pa[idx] = pi_logits[idx];
    __syncthreads();
    if (tid < KST) {
        float m = -1e30f;
        for (int i = 0; i < KST; i++) m = fmaxf(m, Pa[tid * KST + i]);
        float s = 0.f;
        for (int i = 0; i < KST; i++) s += expf(Pa[tid * KST + i] - m);
        rm[tid] = m; ri[tid] = 1.f / s;
    }
    __syncthreads();

    // Pack P operand pairs: fwd thread jj needs column jj; bwd needs row jj.
    u64t Preg2[32];
    if (ch == 0) {
        #pragma unroll
        for (int ii = 0; ii < 32; ii++) {
            float lo = expf(Pa[(2 * ii) * KST + jj] - rm[2 * ii]) * ri[2 * ii];
            float hi = expf(Pa[(2 * ii + 1) * KST + jj] - rm[2 * ii + 1]) * ri[2 * ii + 1];
            Preg2[ii] = pack2(lo, hi);
        }
    } else {
        #pragma unroll
        for (int ii = 0; ii < 32; ii++) {
            float lo = expf(Pa[jj * KST + 2 * ii] - rm[jj]) * ri[jj];
            float hi = expf(Pa[jj * KST + 2 * ii + 1] - rm[jj]) * ri[jj];
            Preg2[ii] = pack2(lo, hi);
        }
    }

    // ---- init carried state ----
    float myu;
    if (ch == 0) {
        if (cb == 0) {
            float pr = 1.f;
            for (int i = 0; i < jj; i++) {
                float sg = 1.f / (1.f + expf(-beta_logits[i]));
                pr *= (1.f - sg);
            }
            float bw = pr / (1.f + expf(-beta_logits[jj]));
            myu = bw * g_E[jj];
            dbuf[0][init_par][jj] = myu;
            g_dirF[jj] = myu;
        } else {
            myu = 1.f / 64.f;
            dbuf[0][init_par][jj] = myu;
        }
    } else {
        myu = 1.f / 64.f;
        if (cb == 0) {
            dbuf[1][init_par][jj] = (1.f / 64.f) * g_E[(size_t)(TLEN - 1) * KST + jj];
            g_dirB[(size_t)(TLEN - 1) * KST + jj] = 1.f / 64.f;
            if (jj == 0) g_cB[0] = 1.0f;
        } else {
            int tws = TLEN - sfirst0;
            dbuf[1][init_par][jj] = (1.f / 64.f) * g_E[(size_t)tws * KST + jj];
        }
    }
    {
        float red = myu;
        red += __shfl_xor_sync(FULL, red, 16);
        red += __shfl_xor_sync(FULL, red, 8);
        red += __shfl_xor_sync(FULL, red, 4);
        red += __shfl_xor_sync(FULL, red, 2);
        red += __shfl_xor_sync(FULL, red, 1);
        if (lane == 0) wsp[init_par][warpid] = red;
    }
    __syncthreads();

    int par = init_par ^ ((sfirst_act - sfirst0) & 1) ^ ((0) & 1);
    par = init_par;                    // par at slot sfirst0 parity base
    // NOTE: loop flips par every step; dbuf valid at par==init_par when s==sfirst_act.
    // We advance par from slot 0: set par so that at s==sfirst_act, par==init_par.
    par = (init_par - (sfirst_act - sfirst0)) & 1;  // == 0 always, kept for clarity

    float* carr = ch ? g_cB : g_cF;
    const int mycmin = ch ? cminB : cmin;

    for (int tb = 0; tb < NTILES; tb++) {
        if (tb + 1 < NTILES) {
            int buf = (tb + 1) & 1;
            #pragma unroll
            for (int i = 0; i < 4; i++) {
                int f = tid + i * 128;
                int c2 = f >> 8, q = (f >> 4) & 15, k0 = (f & 15) << 2;
                int s = sfirst0 + (tb + 1) * TILE + q;
                int row = c2 ? (TLEN - 1 - s) : s;
                row = row < 0 ? 0 : row;
                cp16(&Ebuf[buf][c2][q][k0], g_E + (size_t)row * KST + k0);
            }
            CP_COMMIT();
            CP_WAIT(1);
        } else {
            CP_WAIT(0);
        }
        __syncthreads();

        const float* Etile = &Ebuf[tb & 1][ch][0][0];
        #pragma unroll 2
        for (int st = 0; st < TILE; st++) {
            int s = sfirst0 + tb * TILE + st;
            bool active = (s >= sfirst_act);

            float sp = wsp[par][ch * 2] + wsp[par][ch * 2 + 1];
            float inv = __fdividef(1.f, sp);
            if (jj == 0 && active && (s - 1) >= mycmin) carr[s - 1] = sp;

            const ulonglong2* dc = reinterpret_cast<const ulonglong2*>(&dbuf[ch][par][0]);
            u64t a0 = 0, a1 = 0, a2 = 0, a3 = 0;
            #pragma unroll
            for (int q = 0; q < 16; q += 2) {
                ulonglong2 v = dc[q];
                ulonglong2 w = dc[q + 1];
                fma2(a0, v.x, Preg2[2 * q]);
                fma2(a1, v.y, Preg2[2 * q + 1]);
                fma2(a2, w.x, Preg2[2 * q + 2]);
                fma2(a3, w.y, Preg2[2 * q + 3]);
            }
            add2(a0, a0, a1);
            add2(a2, a2, a3);
            add2(a0, a0, a2);
            float acc = unpack_sum(a0);

            float e = Etile[st * KST + jj];
            int np = par ^ 1;
            if (active) {
                float u;
                if (ch == 0) {
                    u = acc * inv * e;
                    dbuf[0][np][jj] = u;
                    if (s >= sout0) g_dirF[(size_t)s * KST + jj] = u;
                } else {
                    u = acc * inv;
                    dbuf[1][np][jj] = u * e;
                    if (s >= sout0) g_dirB[(size_t)(TLEN - 1 - s) * KST + jj] = u;
                }
                float red = u;
                red += __shfl_xor_sync(FULL, red, 16);
                red += __shfl_xor_sync(FULL, red, 8);
                red += __shfl_xor_sync(FULL, red, 4);
                red += __shfl_xor_sync(FULL, red, 2);
                red += __shfl_xor_sync(FULL, red, 1);
                if (lane == 0) wsp[np][warpid] = red;
            }
            par = np;
            __syncthreads();
        }
    }
    if (jj == 0) carr[send - 1] = wsp[par][ch * 2] + wsp[par][ch * 2 + 1];
}

// ---------------------------------------------------------------------------
// Scale scans: log q_t = S_t + LSE_{j<=t} G_j ; S = prefix sum of log(eps/c).
// ---------------------------------------------------------------------------
__device__ __forceinline__ double lae(double a, double b) {
    double m = fmax(a, b), n = fmin(a, b);
    if (m <= -1e290) return m;
    return m + log1p(exp(n - m));
}

__global__ void scan_k1() {
    __shared__ double sm[512];
    int fb = blockIdx.x >> 9, blk = blockIdx.x & 511;
    const float* carr = fb ? g_cB : g_cF;
    double* S = fb ? g_SB : g_SF;
    int tid = threadIdx.x, idx = blk * 512 + tid;
    double v = (idx == 0) ? 0.0 : (LOGEPS - log((double)carr[idx]));
    sm[tid] = v; __syncthreads();
    for (int off = 1; off < 512; off <<= 1) {
        double t = (tid >= off) ? sm[tid - off] : 0.0;
        __syncthreads();
        sm[tid] += t; __syncthreads();
    }
    S[idx] = sm[tid];
    if (tid == 511) g_part[blockIdx.x] = sm[tid];
}
__global__ void scan_k2() {
    __shared__ double sm[512];
    int tid = threadIdx.x;
    double* p = g_part + blockIdx.x * 512;
    sm[tid] = p[tid]; __syncthreads();
    for (int off = 1; off < 512; off <<= 1) {
        double t = (tid >= off) ? sm[tid - off] : 0.0;
        __syncthreads();
        sm[tid] += t; __syncthreads();
    }
    p[tid] = (tid == 0) ? 0.0 : sm[tid - 1];
}
__global__ void scan_k3() {
    __shared__ double sm[512];
    int fb = blockIdx.x >> 9, blk = blockIdx.x & 511;
    double* S = fb ? g_SB : g_SF;
    double* L = fb ? g_LB : g_LF;
    int tid = threadIdx.x, idx = blk * 512 + tid;
    double s_loc = S[idx] + g_part[blockIdx.x];
    S[idx] = s_loc;
    double g;
    if (idx == 0) g = fb ? -log(64.0) : log1p(EPSV / (double)g_cF[0]);
    else          g = -s_loc;
    sm[tid] = g; __syncthreads();
    for (int off = 1; off < 512; off <<= 1) {
        double t = (tid >= off) ? sm[tid - off] : -1e300;
        __syncthreads();
        sm[tid] = lae(sm[tid], t); __syncthreads();
    }
    L[idx] = sm[tid];
    if (tid == 511) g_part2[blockIdx.x] = sm[tid];
}
__global__ void scan_k4() {
    __shared__ double sm[512];
    int tid = threadIdx.x;
    double* p = g_part2 + blockIdx.x * 512;
    sm[tid] = p[tid]; __syncthreads();
    for (int off = 1; off < 512; off <<= 1) {
        double t = (tid >= off) ? sm[tid - off] : -1e300;
        __syncthreads();
        sm[tid] = lae(sm[tid], t); __syncthreads();
    }
    p[tid] = (tid == 0) ? -1e300 : sm[tid - 1];
}
__global__ void scan_k5(float* __restrict__ out) {
    int fb = blockIdx.x >> 9, blk = blockIdx.x & 511;
    const double* S = fb ? g_SB : g_SF;
    const double* L = fb ? g_LB : g_LF;
    const float* carr = fb ? g_cB : g_cF;
    int idx = blk * 512 + threadIdx.x;
    double lq = S[idx] + lae(L[idx], g_part2[blockIdx.x]);
    float sc = (float)(exp(-lq) / (double)carr[idx]);
    (fb ? g_scB : g_scF)[idx] = sc;
    if (fb == 0 && idx == TLEN - 1)
        out[(size_t)2 * TLEN * KST] = (float)log(exp(-lq) + EPSV);
}

// ---------------------------------------------------------------------------
__global__ void finalize_kernel(float* __restrict__ out) {
    size_t i4 = ((size_t)blockIdx.x * 256 + threadIdx.x) * 4;
    int t = (int)(i4 >> 6);
    float sF = g_scF[t];
    float sB = g_scB[TLEN - 1 - t];
    float4 a = *reinterpret_cast<const float4*>(&g_dirF[i4]);
    float4 b = *reinterpret_cast<const float4*>(&g_dirB[i4]);
    a.x *= sF; a.y *= sF; a.z *= sF; a.w *= sF;
    b.x *= sB; b.y *= sB; b.z *= sB; b.w *= sB;
    *reinterpret_cast<float4*>(&out[i4]) = a;
    *reinterpret_cast<float4*>(&out[(size_t)TLEN * KST + i4]) = b;
}

// ---------------------------------------------------------------------------
extern "C" void kernel_launch(void* const* d_in, const int* in_sizes, int n_in,
                              void* d_out, int out_size) {
    const float* obs      = (const float*)d_in[0];
    const float* blogits  = (const float*)d_in[1];
    const float* pilogits = (const float*)d_in[2];
    const float* means    = (const float*)d_in[3];
    const float* logvars  = (const float*)d_in[4];
    float* out = (float*)d_out;

    emis_kernel<<<TLEN / 4, 256>>>(obs, means, logvars);
    chunk_kernel<<<NCH, 128>>>(pilogits, blogits);
    scan_k1<<<1024, 512>>>();
    scan_k2<<<2, 512>>>();
    scan_k3<<<1024, 512>>>();
    scan_k4<<<2, 512>>>();
    scan_k5<<<1024, 512>>>(out);
    finalize_kernel<<<(size_t)TLEN * KST / 1024, 256>>>(out);
}